// round 1
// baseline (speedup 1.0000x reference)
#include <cuda_runtime.h>
#include <cstdint>

#define BDIM 8
#define LDIM 2048
#define DDIM 1024
#define CH   341
#define NP   384
#define MT   64
#define KC   16
#define NSEG 512

// ---------------- device scratch (static allocations are allowed) ----------------
__device__ float          g_Wr[3 * 1024 * NP];     // [(k*1024+d)*NP + c], zero padded
__device__ float          g_w2p[NP];
__device__ float          g_b1p[NP];
__device__ float          g_logits[BDIM * LDIM];   // logit at position p (p>=2 written)
__device__ unsigned short g_seg[BDIM * LDIM];
__device__ int            g_count[BDIM * NSEG];
__device__ int            g_len[BDIM];
__device__ float          g_pe[NSEG * DDIM];

// ---------------- weight reorder + padding ----------------
__global__ void k_reorder(const float* __restrict__ w1, const float* __restrict__ b1,
                          const float* __restrict__ w2) {
    int idx = blockIdx.x * blockDim.x + threadIdx.x;
    const int total = 3 * 1024 * NP;
    if (idx < total) {
        int c  = idx % NP;
        int kd = idx / NP;
        int k  = kd / 1024;
        int d  = kd % 1024;
        g_Wr[idx] = (c < CH) ? w1[(c * 1024 + d) * 3 + k] : 0.f;
    }
    if (idx < NP) {
        g_w2p[idx] = (idx < CH) ? w2[idx] : 0.f;
        g_b1p[idx] = (idx < CH) ? b1[idx] : 0.f;
    }
}

// ---------------- sinusoidal PE table (double-precision reduction) ----------------
__global__ void k_pe() {
    int idx = blockIdx.x * blockDim.x + threadIdx.x;
    if (idx < NSEG * DDIM) {
        int s  = idx >> 10;
        int d  = idx & 1023;
        int i2 = d & ~1;
        float freqf = expf(-logf(10000.f) * (float)i2 / 1024.f);   // matches f32 div
        float angf  = (float)s * freqf;                            // f32 rounding like numpy
        double ang  = (double)angf;
        g_pe[idx] = (d & 1) ? (float)cos(ang) : (float)sin(ang);
    }
}

// ---------------- zero pooled-sum region + the two scalars ----------------
__global__ void k_zero(float* __restrict__ out, int n) {
    int idx = blockIdx.x * blockDim.x + threadIdx.x;
    if (idx < n) out[idx] = 0.f;
}

// ---------------- conv GEMM: 64 rows x 384 chan, fp32x2 FMA ----------------
__device__ __forceinline__ unsigned long long pack2(float x) {
    unsigned long long r;
    unsigned u = __float_as_uint(x);
    asm("mov.b64 %0, {%1, %1};" : "=l"(r) : "r"(u));
    return r;
}

__global__ __launch_bounds__(256) void k_conv(const float* __restrict__ hidden,
                                              const float* __restrict__ b2) {
    __shared__ __align__(16) float Hs[MT][KC];       // [l_local][dl]
    __shared__ __align__(16) float Ws[KC][NP];       // [dl][c]
    __shared__ float sb1[NP], sw2[NP];

    const int b   = blockIdx.y;
    const int l0  = blockIdx.x * MT;
    const int tid = threadIdx.x;
    const int tx  = tid & 31;
    const int ty  = tid >> 5;

    for (int i = tid; i < NP; i += 256) { sb1[i] = g_b1p[i]; sw2[i] = g_w2p[i]; }

    unsigned long long acc[8][6];
#pragma unroll
    for (int i = 0; i < 8; i++)
#pragma unroll
        for (int j = 0; j < 6; j++) acc[i][j] = 0ULL;

    const float* hb = hidden + (size_t)b * LDIM * DDIM;

    for (int k = 0; k < 3; k++) {
        for (int d0 = 0; d0 < DDIM; d0 += KC) {
            __syncthreads();
            // load H tile: 64 rows x 16 d
            {
                int r = tid >> 2, g = tid & 3;
                int row = l0 + k + r;
                float4 v = make_float4(0.f, 0.f, 0.f, 0.f);
                if (row < LDIM) v = *(const float4*)(hb + (size_t)row * DDIM + d0 + g * 4);
                *(float4*)&Hs[r][g * 4] = v;
            }
            // load W tile: 16 x 384 (coalesced over c)
            {
                const float* wsrc = g_Wr + (size_t)(k * 1024 + d0) * NP;
#pragma unroll
                for (int t = 0; t < 6; t++) {
                    int idx4 = tid + t * 256;     // 0..1535
                    int dl   = idx4 / 96;
                    int cp   = (idx4 % 96) * 4;
                    *(float4*)&Ws[dl][cp] = *(const float4*)(wsrc + dl * NP + cp);
                }
            }
            __syncthreads();
#pragma unroll
            for (int dl = 0; dl < KC; dl++) {
                unsigned long long hh[8];
#pragma unroll
                for (int i = 0; i < 8; i++) hh[i] = pack2(Hs[ty + i * 8][dl]);
#pragma unroll
                for (int j = 0; j < 6; j++) {
                    unsigned long long wp =
                        *(const unsigned long long*)&Ws[dl][2 * (tx + j * 32)];
#pragma unroll
                    for (int i = 0; i < 8; i++)
                        asm("fma.rn.f32x2 %0, %1, %2, %0;"
                            : "+l"(acc[i][j]) : "l"(hh[i]), "l"(wp));
                }
            }
        }
    }

    // epilogue: relu(acc + b1) * w2 summed over channels -> logit
    float b2v = b2[0];
#pragma unroll
    for (int i = 0; i < 8; i++) {
        float s = 0.f;
#pragma unroll
        for (int j = 0; j < 6; j++) {
            float a0 = __uint_as_float((unsigned)(acc[i][j] & 0xffffffffULL));
            float a1 = __uint_as_float((unsigned)(acc[i][j] >> 32));
            int c0 = 2 * (tx + j * 32);
            s += fmaxf(a0 + sb1[c0], 0.f) * sw2[c0];
            s += fmaxf(a1 + sb1[c0 + 1], 0.f) * sw2[c0 + 1];
        }
#pragma unroll
        for (int o = 16; o > 0; o >>= 1) s += __shfl_xor_sync(0xffffffffu, s, o);
        if (tx == 0) {
            int l = l0 + ty + i * 8;
            if (l < LDIM - 2) g_logits[b * LDIM + l + 2] = s + b2v;
        }
    }
}

// ---------------- per-batch: hard bits, seg scan, counts, short_mask, scalars ----
__global__ void k_scan(const float* __restrict__ mask, float* __restrict__ out_short,
                       float* __restrict__ out_scalars) {
    const int b   = blockIdx.x;
    const int tid = threadIdx.x;    // 256
    __shared__ int sh_red[256];
    __shared__ unsigned char sh_hard[LDIM];
    __shared__ int sh_scan[256];
    __shared__ int sh_len;
    __shared__ int sh_count[NSEG];

    const float* mb = mask + b * LDIM;
    int ls = 0;
    for (int p = tid; p < LDIM; p += 256) ls += (mb[p] > 0.5f) ? 1 : 0;
    sh_red[tid] = ls;
    __syncthreads();
    for (int o = 128; o > 0; o >>= 1) {
        if (tid < o) sh_red[tid] += sh_red[tid + o];
        __syncthreads();
    }
    if (tid == 0) sh_len = sh_red[0];
    __syncthreads();
    const int len = sh_len;

    for (int p = tid; p < LDIM; p += 256) {
        int bit = (p >= 2 && p < len && g_logits[b * LDIM + p] > 0.f) ? 1 : 0;
        sh_hard[p] = (unsigned char)bit;
    }
    __syncthreads();
    if (tid == 0 && len < LDIM) sh_hard[len - 1] = 1;   // forced boundary at last real
    for (int s = tid; s < NSEG; s += 256) sh_count[s] = 0;
    __syncthreads();

    // exclusive scan: 8 contiguous per thread
    const int base = tid * 8;
    int t = 0;
    for (int q = 0; q < 8; q++) t += sh_hard[base + q];
    sh_scan[tid] = t;
    __syncthreads();
    for (int o = 1; o < 256; o <<= 1) {
        int v = sh_scan[tid];
        int u = (tid >= o) ? sh_scan[tid - o] : 0;
        __syncthreads();
        sh_scan[tid] = v + u;
        __syncthreads();
    }
    const int nb = sh_scan[255];
    int run = sh_scan[tid] - t;
    for (int q = 0; q < 8; q++) {
        int p = base + q;
        g_seg[b * LDIM + p] = (unsigned short)run;
        if (p < len && run < NSEG) atomicAdd(&sh_count[run], 1);
        run += sh_hard[p];
    }
    __syncthreads();
    for (int s = tid; s < NSEG; s += 256) g_count[b * NSEG + s] = sh_count[s];
    for (int s = tid; s < NSEG; s += 256) out_short[b * NSEG + s] = (s < nb) ? 1.f : 0.f;
    if (tid == 0) {
        g_len[b] = len;
        atomicAdd(&out_scalars[0], (float)nb);
        atomicAdd(&out_scalars[1], (float)len);
    }
}

// ---------------- segment-sum pooling (chunked, atomic flushes) ----------------
__global__ __launch_bounds__(256) void k_pool(const float* __restrict__ hidden,
                                              float* __restrict__ pooled) {
    const int b   = blockIdx.y;
    const int c0  = blockIdx.x * 128;
    const int tid = threadIdx.x;   // 256
    __shared__ unsigned short sseg[128];
    const int len = g_len[b];
    if (c0 >= len) return;
    if (tid < 128) sseg[tid] = g_seg[b * LDIM + c0 + tid];
    __syncthreads();

    const int d = tid * 4;
    const float* hb = hidden + ((size_t)b * LDIM + c0) * DDIM + d;
    float4 acc = make_float4(0.f, 0.f, 0.f, 0.f);
    int cur = sseg[0];
    const int lim = min(128, len - c0);
    for (int li = 0; li < lim; li++) {
        int s = sseg[li];
        if (s != cur) {
            if (cur < NSEG) {
                float* pp = pooled + ((size_t)b * NSEG + cur) * DDIM + d;
                atomicAdd(pp + 0, acc.x); atomicAdd(pp + 1, acc.y);
                atomicAdd(pp + 2, acc.z); atomicAdd(pp + 3, acc.w);
            }
            acc = make_float4(0.f, 0.f, 0.f, 0.f);
            cur = s;
        }
        float4 v = *(const float4*)(hb + (size_t)li * DDIM);
        acc.x += v.x; acc.y += v.y; acc.z += v.z; acc.w += v.w;
    }
    if (cur < NSEG) {
        float* pp = pooled + ((size_t)b * NSEG + cur) * DDIM + d;
        atomicAdd(pp + 0, acc.x); atomicAdd(pp + 1, acc.y);
        atomicAdd(pp + 2, acc.z); atomicAdd(pp + 3, acc.w);
    }
}

// ---------------- finalize: mean + PE ----------------
__global__ void k_final(float* __restrict__ out) {
    int idx = blockIdx.x * blockDim.x + threadIdx.x;
    if (idx < BDIM * NSEG * DDIM) {
        int sd = idx & (NSEG * DDIM - 1);
        int s  = (idx >> 10) & (NSEG - 1);
        int b  = idx >> 19;
        int cnt = g_count[b * NSEG + s];
        out[idx] = out[idx] / ((float)cnt + 1e-9f) + g_pe[sd];
    }
}

// ---------------- launch ----------------
extern "C" void kernel_launch(void* const* d_in, const int* in_sizes, int n_in,
                              void* d_out, int out_size) {
    const float* hidden = (const float*)d_in[0];
    const float* amask  = (const float*)d_in[1];
    const float* w1     = (const float*)d_in[2];
    const float* b1     = (const float*)d_in[3];
    const float* w2     = (const float*)d_in[4];
    const float* b2     = (const float*)d_in[5];
    float* out = (float*)d_out;

    // output layout: pooled (8*512*1024) | num_boundaries | total_positions | short_mask (8*512)
    const int pooled_n  = BDIM * NSEG * DDIM;
    float* out_scalars  = out + (out_size - BDIM * NSEG - 2);
    float* out_short    = out + (out_size - BDIM * NSEG);

    // zero pooled sums + scalars (contiguous region)
    {
        int n = pooled_n + 2;
        k_zero<<<(n + 255) / 256, 256>>>(out, n);
    }
    k_reorder<<<(3 * 1024 * NP + 255) / 256, 256>>>(w1, b1, w2);
    k_pe<<<(NSEG * DDIM + 255) / 256, 256>>>();

    k_conv<<<dim3(32, BDIM), 256>>>(hidden, b2);
    k_scan<<<BDIM, 256>>>(amask, out_short, out_scalars);
    k_pool<<<dim3(16, BDIM), 256>>>(hidden, out);
    k_final<<<(pooled_n + 255) / 256, 256>>>(out);
}

// round 6
// speedup vs baseline: 4.0637x; 4.0637x over previous
#include <cuda_runtime.h>
#include <cuda_bf16.h>
#include <cstdint>

#define BDIM 8
#define LDIM 2048
#define DDIM 1024
#define CH   341
#define NP   384
#define NSEG 512
#define KTOT 3072
#define NCHUNK 48           // KTOT / 64
#define ASTRIDE 72          // 64 + 8 pad (bf16 elements)

// ---------------- device scratch ----------------
__device__ __nv_bfloat16 g_hbf[BDIM * LDIM * DDIM];
__device__ __nv_bfloat16 g_Wbf[NP * KTOT];            // [c][k*1024+d]
__device__ float          g_w2p[NP];
__device__ float          g_b1p[NP];
__device__ float          g_logits[BDIM * LDIM];
__device__ unsigned short g_seg[BDIM * LDIM];
__device__ int            g_count[BDIM * NSEG];
__device__ int            g_len[BDIM];
__device__ float          g_pe[NSEG * DDIM];
__device__ int            g_fix_cnt;
__device__ int            g_fix_list[16384];

__device__ __forceinline__ uint32_t smem_u32(const void* p) {
    uint32_t a;
    asm("{ .reg .u64 t; cvta.to.shared.u64 t, %1; cvt.u32.u64 %0, t; }" : "=r"(a) : "l"(p));
    return a;
}

// ---------------- conversion / setup kernels ----------------
__global__ void k_convert(const float* __restrict__ h) {
    const float4* src = (const float4*)h;
    uint2* dst = (uint2*)g_hbf;
    for (int i = blockIdx.x * blockDim.x + threadIdx.x; i < BDIM * LDIM * DDIM / 4;
         i += gridDim.x * blockDim.x) {
        float4 v = src[i];
        __nv_bfloat162 lo = __floats2bfloat162_rn(v.x, v.y);
        __nv_bfloat162 hi = __floats2bfloat162_rn(v.z, v.w);
        uint2 o;
        o.x = *reinterpret_cast<uint32_t*>(&lo);
        o.y = *reinterpret_cast<uint32_t*>(&hi);
        dst[i] = o;
    }
}

__global__ void k_reorderW(const float* __restrict__ w1, const float* __restrict__ b1,
                           const float* __restrict__ w2) {
    int idx = blockIdx.x * blockDim.x + threadIdx.x;
    if (idx < NP * KTOT) {
        int c = idx / KTOT, r = idx % KTOT;
        int k = r >> 10, d = r & 1023;
        float v = (c < CH) ? w1[((size_t)c * 1024 + d) * 3 + k] : 0.f;
        g_Wbf[idx] = __float2bfloat16(v);
    }
    if (idx < NP) {
        g_w2p[idx] = (idx < CH) ? w2[idx] : 0.f;
        g_b1p[idx] = (idx < CH) ? b1[idx] : 0.f;
    }
    if (idx < BDIM * LDIM) g_logits[idx] = 0.f;
    if (idx == 0) g_fix_cnt = 0;
}

__global__ void k_pe() {
    int idx = blockIdx.x * blockDim.x + threadIdx.x;
    if (idx < NSEG * DDIM) {
        int s = idx >> 10, d = idx & 1023;
        float freq = expf(-logf(10000.f) * (float)(d & ~1) / 1024.f);
        float ang = (float)s * freq;
        g_pe[idx] = (d & 1) ? cosf(ang) : sinf(ang);
    }
}

__global__ void k_zero(float* __restrict__ out, int n) {
    int idx = blockIdx.x * blockDim.x + threadIdx.x;
    if (idx < n) out[idx] = 0.f;
}

// ---------------- conv GEMM: warp-level bf16 mma.sync ----------------
// CTA: M=128 (blockIdx.x), N=128 channels (blockIdx.y), batch (blockIdx.z).
// 8 warps as 4 (M) x 2 (N). Warp tile 32 x 64. K chunked by 64, cp.async 2-stage.
__global__ __launch_bounds__(256) void k_conv(const float* __restrict__ dummy) {
    extern __shared__ __align__(16) char smem[];
    const uint32_t sb = smem_u32(smem);
    const int tid  = threadIdx.x;
    const int lane = tid & 31;
    const int wid  = tid >> 5;
    const int wm   = wid >> 1;          // 0..3
    const int wn   = wid & 1;           // 0..1
    const int b    = blockIdx.z;
    const int l0   = blockIdx.x * 128;
    const int n0   = blockIdx.y * 128;  // channel base

    const __nv_bfloat16* hbf = g_hbf;
    const __nv_bfloat16* wbf = g_Wbf;

    // stage offsets (bytes): A[s] = s*18432, B[s] = 36864 + s*18432
    auto load_stage = [&](int c, int s) {
        const int k  = c >> 4;
        const int d0 = (c & 15) * 64;
        const int kc = c * 64;
        const uint32_t abase = sb + (unsigned)s * 18432u;
        const uint32_t bbase = sb + 36864u + (unsigned)s * 18432u;
#pragma unroll
        for (int i = 0; i < 4; i++) {
            int idx = tid + i * 256;            // 0..1023
            int r = idx >> 3, c8 = idx & 7;
            long grow = (long)b * LDIM + l0 + k + r;
            const __nv_bfloat16* src = hbf + grow * DDIM + d0 + c8 * 8;
            uint32_t dst = abase + (uint32_t)(r * ASTRIDE * 2 + c8 * 16);
            unsigned nb = (grow < (long)BDIM * LDIM) ? 16u : 0u;
            asm volatile("cp.async.cg.shared.global [%0], [%1], 16, %2;"
                         :: "r"(dst), "l"(src), "r"(nb) : "memory");
        }
#pragma unroll
        for (int i = 0; i < 4; i++) {
            int idx = tid + i * 256;
            int r = idx >> 3, c8 = idx & 7;
            const __nv_bfloat16* src = wbf + (size_t)(n0 + r) * KTOT + kc + c8 * 8;
            uint32_t dst = bbase + (uint32_t)(r * ASTRIDE * 2 + c8 * 16);
            asm volatile("cp.async.cg.shared.global [%0], [%1], 16;"
                         :: "r"(dst), "l"(src) : "memory");
        }
        asm volatile("cp.async.commit_group;" ::: "memory");
    };

    float acc[2][8][4];
#pragma unroll
    for (int i = 0; i < 2; i++)
#pragma unroll
        for (int j = 0; j < 8; j++)
#pragma unroll
            for (int e = 0; e < 4; e++) acc[i][j][e] = 0.f;

    load_stage(0, 0);

    for (int c = 0; c < NCHUNK; c++) {
        const int s = c & 1;
        if (c + 1 < NCHUNK) {
            load_stage(c + 1, (c + 1) & 1);
            asm volatile("cp.async.wait_group 1;" ::: "memory");
        } else {
            asm volatile("cp.async.wait_group 0;" ::: "memory");
        }
        __syncthreads();

        const uint32_t abase = sb + (unsigned)s * 18432u;
        const uint32_t bbase = sb + 36864u + (unsigned)s * 18432u;

#pragma unroll
        for (int kk = 0; kk < 4; kk++) {
            // A fragments: 2 x (16x16)
            uint32_t af[2][4];
#pragma unroll
            for (int i = 0; i < 2; i++) {
                int row = wm * 32 + i * 16 + (lane & 15);
                int col = kk * 16 + (lane >> 4) * 8;
                uint32_t addr = abase + (uint32_t)(row * ASTRIDE + col) * 2u;
                asm volatile(
                    "ldmatrix.sync.aligned.m8n8.x4.shared.b16 {%0,%1,%2,%3}, [%4];"
                    : "=r"(af[i][0]), "=r"(af[i][1]), "=r"(af[i][2]), "=r"(af[i][3])
                    : "r"(addr));
            }
            // B fragments: 8 x (8x16), loaded as 4 ldmatrix.x4 (2 frags each)
            uint32_t bf[8][2];
#pragma unroll
            for (int jp = 0; jp < 4; jp++) {
                int grp = lane >> 3;               // 0..3
                int nrow = wn * 64 + jp * 16 + (grp >> 1) * 8 + (lane & 7);
                int col  = kk * 16 + (grp & 1) * 8;
                uint32_t addr = bbase + (uint32_t)(nrow * ASTRIDE + col) * 2u;
                asm volatile(
                    "ldmatrix.sync.aligned.m8n8.x4.shared.b16 {%0,%1,%2,%3}, [%4];"
                    : "=r"(bf[jp * 2][0]), "=r"(bf[jp * 2][1]),
                      "=r"(bf[jp * 2 + 1][0]), "=r"(bf[jp * 2 + 1][1])
                    : "r"(addr));
            }
#pragma unroll
            for (int i = 0; i < 2; i++)
#pragma unroll
                for (int j = 0; j < 8; j++) {
                    asm volatile(
                        "mma.sync.aligned.m16n8k16.row.col.f32.bf16.bf16.f32 "
                        "{%0,%1,%2,%3}, {%4,%5,%6,%7}, {%8,%9}, {%0,%1,%2,%3};"
                        : "+f"(acc[i][j][0]), "+f"(acc[i][j][1]),
                          "+f"(acc[i][j][2]), "+f"(acc[i][j][3])
                        : "r"(af[i][0]), "r"(af[i][1]), "r"(af[i][2]), "r"(af[i][3]),
                          "r"(bf[j][0]), "r"(bf[j][1]));
                }
        }
        __syncthreads();
    }

    // ---- epilogue: relu(acc + b1) * w2 reduced per row ----
    float* red = (float*)smem;      // 128 floats, smem reused
    if (tid < 128) red[tid] = 0.f;
    __syncthreads();

    const int cbase = n0 + wn * 64 + (lane & 3) * 2;
#pragma unroll
    for (int i = 0; i < 2; i++) {
#pragma unroll
        for (int h = 0; h < 2; h++) {
            float s = 0.f;
#pragma unroll
            for (int j = 0; j < 8; j++) {
                int cc = cbase + j * 8;
                float v0 = acc[i][j][h * 2 + 0];
                float v1 = acc[i][j][h * 2 + 1];
                s += fmaxf(v0 + g_b1p[cc], 0.f) * g_w2p[cc];
                s += fmaxf(v1 + g_b1p[cc + 1], 0.f) * g_w2p[cc + 1];
            }
            int row = wm * 32 + i * 16 + h * 8 + (lane >> 2);
            atomicAdd(&red[row], s);
        }
    }
    __syncthreads();
    if (tid < 128) {
        int l = l0 + tid;
        if (l < LDIM - 2) atomicAdd(&g_logits[b * LDIM + l + 2], red[tid]);
    }
}

// ---------------- add b2, flag near-zero logits ----------------
__global__ void k_flag(const float* __restrict__ b2) {
    int idx = blockIdx.x * blockDim.x + threadIdx.x;
    if (idx < BDIM * (LDIM - 2)) {
        int b = idx / (LDIM - 2), l = idx % (LDIM - 2), p = l + 2;
        float v = g_logits[b * LDIM + p] + b2[0];
        g_logits[b * LDIM + p] = v;
        if (fabsf(v) < 0.3f) {
            int i = atomicAdd(&g_fix_cnt, 1);
            if (i < 16384) g_fix_list[i] = (b << 16) | p;
        }
    }
}

// ---------------- fp32 recompute of flagged logits ----------------
__global__ void k_fix(const float* __restrict__ hidden, const float* __restrict__ w1,
                      const float* __restrict__ b1, const float* __restrict__ w2,
                      const float* __restrict__ b2) {
    __shared__ float sred[256];
    int n = g_fix_cnt;
    if (n > 16384) n = 16384;
    for (int it = blockIdx.x; it < n; it += gridDim.x) {
        int e = g_fix_list[it];
        int b = e >> 16, p = e & 0xffff, l = p - 2;
        const float* hb = hidden + ((size_t)b * LDIM + l) * DDIM;
        float s = 0.f;
        for (int c = threadIdx.x; c < CH; c += 256) {
            float a = 0.f;
            const float* wc = w1 + (size_t)c * 3072;
            for (int d = 0; d < 1024; d++) {
                a += hb[d] * wc[d * 3 + 0];
                a += hb[1024 + d] * wc[d * 3 + 1];
                a += hb[2048 + d] * wc[d * 3 + 2];
            }
            s += fmaxf(a + b1[c], 0.f) * w2[c];
        }
        sred[threadIdx.x] = s;
        __syncthreads();
        for (int o = 128; o > 0; o >>= 1) {
            if (threadIdx.x < o) sred[threadIdx.x] += sred[threadIdx.x + o];
            __syncthreads();
        }
        if (threadIdx.x == 0) g_logits[b * LDIM + p] = sred[0] + b2[0];
        __syncthreads();
    }
}

// ---------------- per-batch scan ----------------
__global__ void k_scan(const float* __restrict__ mask, float* __restrict__ out_short,
                       float* __restrict__ out_scalars) {
    const int b = blockIdx.x;
    const int tid = threadIdx.x;
    __shared__ int sh_red[256];
    __shared__ unsigned char sh_hard[LDIM];
    __shared__ int sh_scan[256];
    __shared__ int sh_len;
    __shared__ int sh_count[NSEG];

    const float* mb = mask + b * LDIM;
    int ls = 0;
    for (int p = tid; p < LDIM; p += 256) ls += (mb[p] > 0.5f) ? 1 : 0;
    sh_red[tid] = ls;
    __syncthreads();
    for (int o = 128; o > 0; o >>= 1) {
        if (tid < o) sh_red[tid] += sh_red[tid + o];
        __syncthreads();
    }
    if (tid == 0) sh_len = sh_red[0];
    __syncthreads();
    const int len = sh_len;

    for (int p = tid; p < LDIM; p += 256) {
        int bit = (p >= 2 && p < len && g_logits[b * LDIM + p] > 0.f) ? 1 : 0;
        sh_hard[p] = (unsigned char)bit;
    }
    __syncthreads();
    if (tid == 0 && len < LDIM) sh_hard[len - 1] = 1;
    for (int s = tid; s < NSEG; s += 256) sh_count[s] = 0;
    __syncthreads();

    const int base = tid * 8;
    int t = 0;
    for (int q = 0; q < 8; q++) t += sh_hard[base + q];
    sh_scan[tid] = t;
    __syncthreads();
    for (int o = 1; o < 256; o <<= 1) {
        int v = sh_scan[tid];
        int u = (tid >= o) ? sh_scan[tid - o] : 0;
        __syncthreads();
        sh_scan[tid] = v + u;
        __syncthreads();
    }
    const int nb = sh_scan[255];
    int run = sh_scan[tid] - t;
    for (int q = 0; q < 8; q++) {
        int p = base + q;
        g_seg[b * LDIM + p] = (unsigned short)run;
        if (p < len && run < NSEG) atomicAdd(&sh_count[run], 1);
        run += sh_hard[p];
    }
    __syncthreads();
    for (int s = tid; s < NSEG; s += 256) g_count[b * NSEG + s] = sh_count[s];
    for (int s = tid; s < NSEG; s += 256) out_short[b * NSEG + s] = (s < nb) ? 1.f : 0.f;
    if (tid == 0) {
        g_len[b] = len;
        atomicAdd(&out_scalars[0], (float)nb);
        atomicAdd(&out_scalars[1], (float)len);
    }
}

// ---------------- segment-sum pooling ----------------
__global__ __launch_bounds__(256) void k_pool(const float* __restrict__ hidden,
                                              float* __restrict__ pooled) {
    const int b = blockIdx.y;
    const int c0 = blockIdx.x * 128;
    const int tid = threadIdx.x;
    __shared__ unsigned short sseg[128];
    const int len = g_len[b];
    if (c0 >= len) return;
    if (tid < 128) sseg[tid] = g_seg[b * LDIM + c0 + tid];
    __syncthreads();

    const int d = tid * 4;
    const float* hb = hidden + ((size_t)b * LDIM + c0) * DDIM + d;
    float4 acc = make_float4(0.f, 0.f, 0.f, 0.f);
    int cur = sseg[0];
    const int lim = min(128, len - c0);
    for (int li = 0; li < lim; li++) {
        int s = sseg[li];
        if (s != cur) {
            if (cur < NSEG) {
                float* pp = pooled + ((size_t)b * NSEG + cur) * DDIM + d;
                atomicAdd(pp + 0, acc.x); atomicAdd(pp + 1, acc.y);
                atomicAdd(pp + 2, acc.z); atomicAdd(pp + 3, acc.w);
            }
            acc = make_float4(0.f, 0.f, 0.f, 0.f);
            cur = s;
        }
        float4 v = *(const float4*)(hb + (size_t)li * DDIM);
        acc.x += v.x; acc.y += v.y; acc.z += v.z; acc.w += v.w;
    }
    if (cur < NSEG) {
        float* pp = pooled + ((size_t)b * NSEG + cur) * DDIM + d;
        atomicAdd(pp + 0, acc.x); atomicAdd(pp + 1, acc.y);
        atomicAdd(pp + 2, acc.z); atomicAdd(pp + 3, acc.w);
    }
}

// ---------------- finalize ----------------
__global__ void k_final(float* __restrict__ out) {
    int idx = blockIdx.x * blockDim.x + threadIdx.x;
    if (idx < BDIM * NSEG * DDIM) {
        int sd = idx & (NSEG * DDIM - 1);
        int s = (idx >> 10) & (NSEG - 1);
        int b = idx >> 19;
        int cnt = g_count[b * NSEG + s];
        out[idx] = out[idx] / ((float)cnt + 1e-9f) + g_pe[sd];
    }
}

// ---------------- launch ----------------
extern "C" void kernel_launch(void* const* d_in, const int* in_sizes, int n_in,
                              void* d_out, int out_size) {
    const float* hidden = (const float*)d_in[0];
    const float* amask  = (const float*)d_in[1];
    const float* w1     = (const float*)d_in[2];
    const float* b1     = (const float*)d_in[3];
    const float* w2     = (const float*)d_in[4];
    const float* b2     = (const float*)d_in[5];
    float* out = (float*)d_out;

    const int pooled_n = BDIM * NSEG * DDIM;
    float* out_scalars = out + (out_size - BDIM * NSEG - 2);
    float* out_short   = out + (out_size - BDIM * NSEG);

    const int smem_bytes = 73728;
    cudaFuncSetAttribute(k_conv, cudaFuncAttributeMaxDynamicSharedMemorySize, smem_bytes);

    k_zero<<<(pooled_n + 2 + 255) / 256, 256>>>(out, pooled_n + 2);
    k_convert<<<2048, 256>>>(hidden);
    k_reorderW<<<(NP * KTOT + 255) / 256, 256>>>(w1, b1, w2);
    k_pe<<<(NSEG * DDIM + 255) / 256, 256>>>();

    k_conv<<<dim3(16, 3, BDIM), 256, smem_bytes>>>(nullptr);
    k_flag<<<(BDIM * (LDIM - 2) + 255) / 256, 256>>>(b2);
    k_fix<<<16, 256>>>(hidden, w1, b1, w2, b2);
    k_scan<<<BDIM, 256>>>(amask, out_short, out_scalars);
    k_pool<<<dim3(16, BDIM), 256>>>(hidden, out);
    k_final<<<(pooled_n + 255) / 256, 256>>>(out);
}

// round 7
// speedup vs baseline: 4.5792x; 1.1269x over previous
#include <cuda_runtime.h>
#include <cuda_bf16.h>
#include <cstdint>

#define BDIM 8
#define LDIM 2048
#define DDIM 1024
#define CH   341
#define NP   384
#define NSEG 512
#define KTOT 3072
#define NCHUNK 48           // KTOT / 64

// ---------------- device scratch ----------------
__device__ __nv_bfloat16 g_hbf[BDIM * LDIM * DDIM];
__device__ __nv_bfloat16 g_Wbf[NP * KTOT];            // [c][k*1024+d]
__device__ float          g_w2p[NP];
__device__ float          g_b1p[NP];
__device__ float          g_logits[BDIM * LDIM];
__device__ unsigned short g_seg[BDIM * LDIM];
__device__ int            g_count[BDIM * NSEG];
__device__ int            g_len[BDIM];
__device__ float          g_pe[NSEG * DDIM];
__device__ int            g_fix_cnt;
__device__ int            g_fix_list[16384];

__device__ __forceinline__ uint32_t smem_u32(const void* p) {
    uint32_t a;
    asm("{ .reg .u64 t; cvta.to.shared.u64 t, %1; cvt.u32.u64 %0, t; }" : "=r"(a) : "l"(p));
    return a;
}

// ---------------- conversion ----------------
__global__ void k_convert(const float* __restrict__ h) {
    const float4* src = (const float4*)h;
    uint2* dst = (uint2*)g_hbf;
    for (int i = blockIdx.x * blockDim.x + threadIdx.x; i < BDIM * LDIM * DDIM / 4;
         i += gridDim.x * blockDim.x) {
        float4 v = src[i];
        __nv_bfloat162 lo = __floats2bfloat162_rn(v.x, v.y);
        __nv_bfloat162 hi = __floats2bfloat162_rn(v.z, v.w);
        uint2 o;
        o.x = *reinterpret_cast<uint32_t*>(&lo);
        o.y = *reinterpret_cast<uint32_t*>(&hi);
        dst[i] = o;
    }
}

// ---------------- fused setup: zero out, reorder W, PE table, init ----------------
__global__ void k_setup(float* __restrict__ out, int nzero,
                        const float* __restrict__ w1, const float* __restrict__ b1,
                        const float* __restrict__ w2) {
    int idx = blockIdx.x * blockDim.x + threadIdx.x;
    if (idx < nzero) out[idx] = 0.f;
    if (idx < NP * KTOT) {
        int c = idx / KTOT, r = idx % KTOT;
        int k = r >> 10, d = r & 1023;
        float v = (c < CH) ? w1[((size_t)c * 1024 + d) * 3 + k] : 0.f;
        g_Wbf[idx] = __float2bfloat16(v);
    }
    if (idx < NSEG * DDIM) {
        int s = idx >> 10, d = idx & 1023;
        float freq = expf(-logf(10000.f) * (float)(d & ~1) / 1024.f);
        float ang = (float)s * freq;
        g_pe[idx] = (d & 1) ? cosf(ang) : sinf(ang);
    }
    if (idx < NP) {
        g_w2p[idx] = (idx < CH) ? w2[idx] : 0.f;
        g_b1p[idx] = (idx < CH) ? b1[idx] : 0.f;
    }
    if (idx < BDIM * LDIM) g_logits[idx] = 0.f;
    if (idx == 0) g_fix_cnt = 0;
}

// ---------------- conv GEMM: warp-level bf16 mma.sync, 3-stage, 2 CTA/SM -------
// CTA: M=128 (bx), N=128 channels (by), batch (bz). 8 warps = 4(M) x 2(N).
// Warp tile 32 x 64. K chunks of 64. XOR-swizzled smem (128B rows, 16B chunks).
__global__ __launch_bounds__(256, 2) void k_conv(const float* __restrict__ dummy) {
    extern __shared__ __align__(128) char smem[];
    const uint32_t sb = smem_u32(smem);
    const int tid  = threadIdx.x;
    const int lane = tid & 31;
    const int wid  = tid >> 5;
    const int wm   = wid >> 1;
    const int wn   = wid & 1;
    const int b    = blockIdx.z;
    const int l0   = blockIdx.x * 128;
    const int n0   = blockIdx.y * 128;

    const __nv_bfloat16* hbf = g_hbf;
    const __nv_bfloat16* wbf = g_Wbf;

    // stage layout: A[s] = s*16384, B[s] = 49152 + s*16384  (3 stages, 96KB)
    auto load_stage = [&](int c, int s) {
        const int k  = c >> 4;
        const int d0 = (c & 15) * 64;
        const int kc = c * 64;
        const uint32_t abase = sb + (unsigned)s * 16384u;
        const uint32_t bbase = sb + 49152u + (unsigned)s * 16384u;
#pragma unroll
        for (int i = 0; i < 4; i++) {
            int idx = tid + i * 256;
            int r = idx >> 3, c8 = idx & 7;
            long grow = (long)b * LDIM + l0 + k + r;
            const __nv_bfloat16* src = hbf + grow * DDIM + d0 + c8 * 8;
            uint32_t dst = abase + (uint32_t)(r * 128 + ((c8 ^ (r & 7)) << 4));
            unsigned nb = (grow < (long)BDIM * LDIM) ? 16u : 0u;
            asm volatile("cp.async.cg.shared.global [%0], [%1], 16, %2;"
                         :: "r"(dst), "l"(src), "r"(nb) : "memory");
        }
#pragma unroll
        for (int i = 0; i < 4; i++) {
            int idx = tid + i * 256;
            int r = idx >> 3, c8 = idx & 7;
            const __nv_bfloat16* src = wbf + (size_t)(n0 + r) * KTOT + kc + c8 * 8;
            uint32_t dst = bbase + (uint32_t)(r * 128 + ((c8 ^ (r & 7)) << 4));
            asm volatile("cp.async.cg.shared.global [%0], [%1], 16;"
                         :: "r"(dst), "l"(src) : "memory");
        }
        asm volatile("cp.async.commit_group;" ::: "memory");
    };

    float acc[2][8][4];
#pragma unroll
    for (int i = 0; i < 2; i++)
#pragma unroll
        for (int j = 0; j < 8; j++)
#pragma unroll
            for (int e = 0; e < 4; e++) acc[i][j][e] = 0.f;

    load_stage(0, 0);
    load_stage(1, 1);

    for (int c = 0; c < NCHUNK; c++) {
        const int s = c % 3;
        if (c + 2 < NCHUNK) {
            load_stage(c + 2, (c + 2) % 3);
            asm volatile("cp.async.wait_group 2;" ::: "memory");
        } else {
            asm volatile("cp.async.wait_group 0;" ::: "memory");
        }
        __syncthreads();

        const uint32_t abase = sb + (unsigned)s * 16384u;
        const uint32_t bbase = sb + 49152u + (unsigned)s * 16384u;

#pragma unroll
        for (int kk = 0; kk < 4; kk++) {
            uint32_t af[2][4];
#pragma unroll
            for (int i = 0; i < 2; i++) {
                int row = wm * 32 + i * 16 + (lane & 15);
                int chk = kk * 2 + (lane >> 4);
                uint32_t addr = abase + (uint32_t)(row * 128 + ((chk ^ (row & 7)) << 4));
                asm volatile(
                    "ldmatrix.sync.aligned.m8n8.x4.shared.b16 {%0,%1,%2,%3}, [%4];"
                    : "=r"(af[i][0]), "=r"(af[i][1]), "=r"(af[i][2]), "=r"(af[i][3])
                    : "r"(addr));
            }
            uint32_t bf[8][2];
#pragma unroll
            for (int jp = 0; jp < 4; jp++) {
                int grp = lane >> 3;
                int nrow = wn * 64 + jp * 16 + (grp >> 1) * 8 + (lane & 7);
                int chk  = kk * 2 + (grp & 1);
                uint32_t addr = bbase + (uint32_t)(nrow * 128 + ((chk ^ (nrow & 7)) << 4));
                asm volatile(
                    "ldmatrix.sync.aligned.m8n8.x4.shared.b16 {%0,%1,%2,%3}, [%4];"
                    : "=r"(bf[jp * 2][0]), "=r"(bf[jp * 2][1]),
                      "=r"(bf[jp * 2 + 1][0]), "=r"(bf[jp * 2 + 1][1])
                    : "r"(addr));
            }
#pragma unroll
            for (int i = 0; i < 2; i++)
#pragma unroll
                for (int j = 0; j < 8; j++) {
                    asm volatile(
                        "mma.sync.aligned.m16n8k16.row.col.f32.bf16.bf16.f32 "
                        "{%0,%1,%2,%3}, {%4,%5,%6,%7}, {%8,%9}, {%0,%1,%2,%3};"
                        : "+f"(acc[i][j][0]), "+f"(acc[i][j][1]),
                          "+f"(acc[i][j][2]), "+f"(acc[i][j][3])
                        : "r"(af[i][0]), "r"(af[i][1]), "r"(af[i][2]), "r"(af[i][3]),
                          "r"(bf[j][0]), "r"(bf[j][1]));
                }
        }
        __syncthreads();
    }

    // ---- epilogue: relu(acc + b1) * w2 reduced per row ----
    float* red = (float*)smem;
    if (tid < 128) red[tid] = 0.f;
    __syncthreads();

    const int cbase = n0 + wn * 64 + (lane & 3) * 2;
#pragma unroll
    for (int i = 0; i < 2; i++) {
#pragma unroll
        for (int h = 0; h < 2; h++) {
            float s = 0.f;
#pragma unroll
            for (int j = 0; j < 8; j++) {
                int cc = cbase + j * 8;
                float v0 = acc[i][j][h * 2 + 0];
                float v1 = acc[i][j][h * 2 + 1];
                s += fmaxf(v0 + g_b1p[cc], 0.f) * g_w2p[cc];
                s += fmaxf(v1 + g_b1p[cc + 1], 0.f) * g_w2p[cc + 1];
            }
            int row = wm * 32 + i * 16 + h * 8 + (lane >> 2);
            atomicAdd(&red[row], s);
        }
    }
    __syncthreads();
    if (tid < 128) {
        int l = l0 + tid;
        if (l < LDIM - 2) atomicAdd(&g_logits[b * LDIM + l + 2], red[tid]);
    }
}

// ---------------- add b2, flag near-zero logits ----------------
__global__ void k_flag(const float* __restrict__ b2) {
    int idx = blockIdx.x * blockDim.x + threadIdx.x;
    if (idx < BDIM * (LDIM - 2)) {
        int b = idx / (LDIM - 2), l = idx % (LDIM - 2), p = l + 2;
        float v = g_logits[b * LDIM + p] + b2[0];
        g_logits[b * LDIM + p] = v;
        if (fabsf(v) < 0.3f) {
            int i = atomicAdd(&g_fix_cnt, 1);
            if (i < 16384) g_fix_list[i] = (b << 16) | p;
        }
    }
}

// ---------------- fp32 recompute of flagged logits ----------------
__global__ void k_fix(const float* __restrict__ hidden, const float* __restrict__ w1,
                      const float* __restrict__ b1, const float* __restrict__ w2,
                      const float* __restrict__ b2) {
    __shared__ float sred[256];
    int n = g_fix_cnt;
    if (n > 16384) n = 16384;
    for (int it = blockIdx.x; it < n; it += gridDim.x) {
        int e = g_fix_list[it];
        int b = e >> 16, p = e & 0xffff, l = p - 2;
        const float* hb = hidden + ((size_t)b * LDIM + l) * DDIM;
        float s = 0.f;
        for (int c = threadIdx.x; c < CH; c += 256) {
            float a = 0.f;
            const float* wc = w1 + (size_t)c * 3072;
            for (int d = 0; d < 1024; d++) {
                a += hb[d] * wc[d * 3 + 0];
                a += hb[1024 + d] * wc[d * 3 + 1];
                a += hb[2048 + d] * wc[d * 3 + 2];
            }
            s += fmaxf(a + b1[c], 0.f) * w2[c];
        }
        sred[threadIdx.x] = s;
        __syncthreads();
        for (int o = 128; o > 0; o >>= 1) {
            if (threadIdx.x < o) sred[threadIdx.x] += sred[threadIdx.x + o];
            __syncthreads();
        }
        if (threadIdx.x == 0) g_logits[b * LDIM + p] = sred[0] + b2[0];
        __syncthreads();
    }
}

// ---------------- per-batch scan ----------------
__global__ void k_scan(const float* __restrict__ mask, float* __restrict__ out_short,
                       float* __restrict__ out_scalars) {
    const int b = blockIdx.x;
    const int tid = threadIdx.x;
    __shared__ int sh_red[256];
    __shared__ unsigned char sh_hard[LDIM];
    __shared__ int sh_scan[256];
    __shared__ int sh_len;
    __shared__ int sh_count[NSEG];

    const float* mb = mask + b * LDIM;
    int ls = 0;
    for (int p = tid; p < LDIM; p += 256) ls += (mb[p] > 0.5f) ? 1 : 0;
    sh_red[tid] = ls;
    __syncthreads();
    for (int o = 128; o > 0; o >>= 1) {
        if (tid < o) sh_red[tid] += sh_red[tid + o];
        __syncthreads();
    }
    if (tid == 0) sh_len = sh_red[0];
    __syncthreads();
    const int len = sh_len;

    for (int p = tid; p < LDIM; p += 256) {
        int bit = (p >= 2 && p < len && g_logits[b * LDIM + p] > 0.f) ? 1 : 0;
        sh_hard[p] = (unsigned char)bit;
    }
    __syncthreads();
    if (tid == 0 && len < LDIM) sh_hard[len - 1] = 1;
    for (int s = tid; s < NSEG; s += 256) sh_count[s] = 0;
    __syncthreads();

    const int base = tid * 8;
    int t = 0;
    for (int q = 0; q < 8; q++) t += sh_hard[base + q];
    sh_scan[tid] = t;
    __syncthreads();
    for (int o = 1; o < 256; o <<= 1) {
        int v = sh_scan[tid];
        int u = (tid >= o) ? sh_scan[tid - o] : 0;
        __syncthreads();
        sh_scan[tid] = v + u;
        __syncthreads();
    }
    const int nb = sh_scan[255];
    int run = sh_scan[tid] - t;
    for (int q = 0; q < 8; q++) {
        int p = base + q;
        g_seg[b * LDIM + p] = (unsigned short)run;
        if (p < len && run < NSEG) atomicAdd(&sh_count[run], 1);
        run += sh_hard[p];
    }
    __syncthreads();
    for (int s = tid; s < NSEG; s += 256) g_count[b * NSEG + s] = sh_count[s];
    for (int s = tid; s < NSEG; s += 256) out_short[b * NSEG + s] = (s < nb) ? 1.f : 0.f;
    if (tid == 0) {
        g_len[b] = len;
        atomicAdd(&out_scalars[0], (float)nb);
        atomicAdd(&out_scalars[1], (float)len);
    }
}

// ---------------- segment-sum pooling ----------------
__global__ __launch_bounds__(256) void k_pool(const float* __restrict__ hidden,
                                              float* __restrict__ pooled) {
    const int b = blockIdx.y;
    const int c0 = blockIdx.x * 128;
    const int tid = threadIdx.x;
    __shared__ unsigned short sseg[128];
    const int len = g_len[b];
    if (c0 >= len) return;
    if (tid < 128) sseg[tid] = g_seg[b * LDIM + c0 + tid];
    __syncthreads();

    const int d = tid * 4;
    const float* hb = hidden + ((size_t)b * LDIM + c0) * DDIM + d;
    float4 acc = make_float4(0.f, 0.f, 0.f, 0.f);
    int cur = sseg[0];
    const int lim = min(128, len - c0);
    for (int li = 0; li < lim; li++) {
        int s = sseg[li];
        if (s != cur) {
            if (cur < NSEG) {
                float* pp = pooled + ((size_t)b * NSEG + cur) * DDIM + d;
                atomicAdd(pp + 0, acc.x); atomicAdd(pp + 1, acc.y);
                atomicAdd(pp + 2, acc.z); atomicAdd(pp + 3, acc.w);
            }
            acc = make_float4(0.f, 0.f, 0.f, 0.f);
            cur = s;
        }
        float4 v = *(const float4*)(hb + (size_t)li * DDIM);
        acc.x += v.x; acc.y += v.y; acc.z += v.z; acc.w += v.w;
    }
    if (cur < NSEG) {
        float* pp = pooled + ((size_t)b * NSEG + cur) * DDIM + d;
        atomicAdd(pp + 0, acc.x); atomicAdd(pp + 1, acc.y);
        atomicAdd(pp + 2, acc.z); atomicAdd(pp + 3, acc.w);
    }
}

// ---------------- finalize ----------------
__global__ void k_final(float* __restrict__ out) {
    int idx = blockIdx.x * blockDim.x + threadIdx.x;
    if (idx < BDIM * NSEG * DDIM) {
        int sd = idx & (NSEG * DDIM - 1);
        int s = (idx >> 10) & (NSEG - 1);
        int b = idx >> 19;
        int cnt = g_count[b * NSEG + s];
        out[idx] = out[idx] / ((float)cnt + 1e-9f) + g_pe[sd];
    }
}

// ---------------- launch ----------------
extern "C" void kernel_launch(void* const* d_in, const int* in_sizes, int n_in,
                              void* d_out, int out_size) {
    const float* hidden = (const float*)d_in[0];
    const float* amask  = (const float*)d_in[1];
    const float* w1     = (const float*)d_in[2];
    const float* b1     = (const float*)d_in[3];
    const float* w2     = (const float*)d_in[4];
    const float* b2     = (const float*)d_in[5];
    float* out = (float*)d_out;

    const int pooled_n = BDIM * NSEG * DDIM;
    float* out_scalars = out + (out_size - BDIM * NSEG - 2);
    float* out_short   = out + (out_size - BDIM * NSEG);

    const int smem_bytes = 98304;   // 3 stages x 32KB
    cudaFuncSetAttribute(k_conv, cudaFuncAttributeMaxDynamicSharedMemorySize, smem_bytes);

    k_setup<<<(pooled_n + 2 + 255) / 256, 256>>>(out, pooled_n + 2, w1, b1, w2);
    k_convert<<<2048, 256>>>(hidden);

    k_conv<<<dim3(16, 3, BDIM), 256, smem_bytes>>>(nullptr);
    k_flag<<<(BDIM * (LDIM - 2) + 255) / 256, 256>>>(b2);
    k_fix<<<16, 256>>>(hidden, w1, b1, w2, b2);
    k_scan<<<BDIM, 256>>>(amask, out_short, out_scalars);
    k_pool<<<dim3(16, BDIM), 256>>>(hidden, out);
    k_final<<<(pooled_n + 255) / 256, 256>>>(out);
}